// round 15
// baseline (speedup 1.0000x reference)
#include <cuda_runtime.h>
#include <cuda_fp16.h>
#include <cstdint>
#include <cstddef>

#define DM   1024
#define NTOK 4096

typedef __half fp16;

// ---------------- scratch ----------------------------------------------------
__device__ float g_Xt [(size_t)NTOK * DM];          // X^T fp32 (residual)
__device__ fp16  g_Xth[(size_t)NTOK * DM];
__device__ fp16  g_Xtl[(size_t)NTOK * DM];
__device__ fp16  g_PAh[(size_t)2 * DM * DM];        // [Wq ; Wv]  straight split hi
__device__ fp16  g_PAl[(size_t)2 * DM * DM];
__device__ fp16  g_PBh[(size_t)2 * DM * DM];        // [Wk ; Wo^T] hi
__device__ fp16  g_PBl[(size_t)2 * DM * DM];
__device__ fp16  g_POh[(size_t)2 * DM * DM];        // [M^T ; Wvo^T] hi
__device__ fp16  g_POl[(size_t)2 * DM * DM];
__device__ fp16  g_W4h[(size_t)DM * DM];            // mlp_in^T hi
__device__ fp16  g_W4l[(size_t)DM * DM];            // (unused)
__device__ fp16  g_W5h[(size_t)DM * DM];            // mlp_out^T hi
__device__ fp16  g_W5l[(size_t)DM * DM];            // (unused)
__device__ fp16  g_Qmh[(size_t)NTOK * DM];          // Xt @ M
__device__ fp16  g_Qml[(size_t)NTOK * DM];
__device__ fp16  g_RHth[(size_t)DM * NTOK];         // (Xt Wvo)^T  [dm][tok]
__device__ fp16  g_RHtl[(size_t)DM * NTOK];         // (unused; kept for layout)
__device__ float g_S  [(size_t)NTOK * NTOK];        // raw scores fp32
__device__ fp16  g_Ah [(size_t)NTOK * NTOK];        // softmax weights, fp16 hi only
__device__ float g_X2 [(size_t)NTOK * DM];          // fp32 (residual)
__device__ fp16  g_X2h[(size_t)NTOK * DM];
__device__ fp16  g_Hh [(size_t)NTOK * DM];

#define NEG_INF (-__int_as_float(0x7f800000))

// ---------------- small helpers ----------------------------------------------
__device__ __forceinline__ uint32_t smem_u32(const void* p) {
    uint32_t a;
    asm("{ .reg .u64 t; cvta.to.shared.u64 t, %1; cvt.u32.u64 %0, t; }"
        : "=r"(a) : "l"(p));
    return a;
}

#define CP16(d, p) \
    asm volatile("cp.async.cg.shared.global [%0], [%1], 16;" :: "r"(d), "l"(p) : "memory")
#define CP_COMMIT()  asm volatile("cp.async.commit_group;" ::: "memory")
#define CP_WAIT1()   asm volatile("cp.async.wait_group 1;" ::: "memory")
#define CP_WAIT0()   asm volatile("cp.async.wait_group 0;" ::: "memory")

#define LDSM4(r0, r1, r2, r3, addr) \
    asm volatile("ldmatrix.sync.aligned.m8n8.x4.shared.b16 {%0,%1,%2,%3}, [%4];" \
        : "=r"(r0), "=r"(r1), "=r"(r2), "=r"(r3) : "r"(addr))

__device__ __forceinline__ void mma16816(float* c, const uint32_t* a, const uint32_t* b) {
    asm volatile(
        "mma.sync.aligned.m16n8k16.row.col.f32.f16.f16.f32 "
        "{%0,%1,%2,%3}, {%4,%5,%6,%7}, {%8,%9}, {%0,%1,%2,%3};"
        : "+f"(c[0]), "+f"(c[1]), "+f"(c[2]), "+f"(c[3])
        : "r"(a[0]), "r"(a[1]), "r"(a[2]), "r"(a[3]), "r"(b[0]), "r"(b[1]));
}

__device__ __forceinline__ void split2(float v, fp16& h, fp16& l) {
    h = __float2half_rn(v);
    l = __float2half_rn(v - __half2float(h));
}

// ---------------- fp16-split GEMM (mma.sync + ldmatrix, 2-stage cp.async) ----
// C[M, Ntot] = A'[M,Ktot] @ B'[Ntot,Ktot]^T
//   TERMS=1: Ah·Bh            TERMS=2: (Ah+Al)·Bh        TERMS=3: +Ah·Bl
// CTA tile 128x128, warp tile 64x32, K-chunk 64.
// EPI: 0  Cf = acc (fp32)
//      1  Ch/Cl = split(acc)
//      2  Ch/Cl = split(relu(acc))
//      3  Cf = acc + R ; Ch/Cl = split(Cf)
//      4  transposed: Ch/Cl[c*ldC + r] = split(acc)
//      5  transposed: Cf[c*ldC + r] = acc + R
//      6  transposed: Ch[c*ldC + r] = half(acc)   (hi only)
//      7  Ch = half(relu(acc))                    (hi only)
//      8  Cf = acc + R ; Ch = half(Cf)            (hi only)
// CMASK: skip CTA tiles fully above causal diagonal
// CKLIM: K-loop bounded to row0+128 (A rows have zeros beyond)
// MINB:  min blocks per SM
// z-batch: blockIdx.z offsets A/B/Ch/Cl pointers by z*DM*DM (for fused preps)

#define TILE_B   18432               // 128 rows * 144B (64 fp16 = 128B + 16B pad)

template<int EPI, int TERMS, int CMASK, int CKLIM, int MINB>
__global__ void __launch_bounds__(256, MINB)
gemm_mma(const fp16* __restrict__ Ahp, const fp16* __restrict__ Alp,
         const fp16* __restrict__ Bhp, const fp16* __restrict__ Blp,
         const float* __restrict__ R,
         float* __restrict__ Cf, fp16* __restrict__ Ch, fp16* __restrict__ Cl,
         int Ntot, int Ktot, int ldC)
{
    constexpr int NA  = (TERMS >= 2) ? 2 : 1;      // A tiles (hi, lo?)
    constexpr int NB  = (TERMS == 3) ? 2 : 1;      // B tiles (hi, lo?)
    constexpr int STB = (NA + NB) * TILE_B;        // stage bytes
    constexpr int BOFF = NA * TILE_B;              // B hi offset within stage

    const int row0 = blockIdx.y * 128;
    const int col0 = blockIdx.x * 128;
    if (CMASK && col0 > row0 + 127) return;

    const size_t zo = (size_t)blockIdx.z * ((size_t)DM * DM);
    Ahp += zo; Bhp += zo; Ch += zo; Cl += zo;
    if (NA == 2) Alp += zo;
    if (NB == 2) Blp += zo;

    extern __shared__ __align__(16) char smem_raw[];
    const uint32_t sbase = smem_u32(smem_raw);

    const int tid  = threadIdx.x;
    const int lane = tid & 31;
    const int wid  = tid >> 5;
    const int wm   = (wid & 1) * 64;
    const int wn   = (wid >> 1) * 32;
    const int gr   = lane >> 2;
    const int lc   = lane & 3;

    // ldmatrix per-lane address components
    const int mi = lane >> 3, ri = lane & 7;
    const uint32_t aoff = (uint32_t)(((mi & 1) * 8 + ri) * 144 + (mi >> 1) * 16);
    const uint32_t boff = (uint32_t)(((mi >> 1) * 8 + ri) * 144 + (mi & 1) * 16);

    int nch = Ktot >> 6;
    if (CKLIM) { int lim = (row0 + 128) >> 6; nch = (lim < nch) ? lim : nch; }

    float acc[4][4][4] = {};

    // ---- loader: one 64-wide K chunk into stage stg ----
    const int ldr  = tid >> 1;        // 0..127 row
    const int lhf  = tid & 1;         // half-row (64B = 4 x 16B)
    auto issue = [&](int ch, int stg) {
        const size_t ko = (size_t)(ch << 6) + (lhf << 5);
        uint32_t dst = sbase + stg * STB + ldr * 144 + lhf * 64;
        const fp16* s0 = Ahp + (size_t)(row0 + ldr) * Ktot + ko;
        const fp16* s2 = Bhp + (size_t)(col0 + ldr) * Ktot + ko;
#pragma unroll
        for (int i = 0; i < 4; i++) CP16(dst + i * 16,          s0 + i * 8);
        if (NA == 2) {
            const fp16* s1 = Alp + (size_t)(row0 + ldr) * Ktot + ko;
#pragma unroll
            for (int i = 0; i < 4; i++) CP16(dst + TILE_B + i * 16, s1 + i * 8);
        }
#pragma unroll
        for (int i = 0; i < 4; i++) CP16(dst + BOFF + i * 16,   s2 + i * 8);
        if (NB == 2) {
            const fp16* s3 = Blp + (size_t)(col0 + ldr) * Ktot + ko;
#pragma unroll
            for (int i = 0; i < 4; i++) CP16(dst + BOFF + TILE_B + i * 16, s3 + i * 8);
        }
        CP_COMMIT();
    };

    issue(0, 0);
    if (nch > 1) issue(1, 1);

    for (int ch = 0; ch < nch; ch++) {
        if (ch + 1 < nch) CP_WAIT1(); else CP_WAIT0();
        __syncthreads();

        const uint32_t stq = sbase + (ch & 1) * STB;
        const uint32_t Abase = stq + wm * 144 + aoff;            // Ah
        const uint32_t Bbase = stq + BOFF + wn * 144 + boff;     // Bh

#pragma unroll
        for (int ks = 0; ks < 4; ks++) {
            const uint32_t ab = Abase + ks * 32;
            const uint32_t bb = Bbase + ks * 32;
            uint32_t ah[4][4], al[4][4], bh[4][2], bl[4][2];
#pragma unroll
            for (int mt = 0; mt < 4; mt++) {
                LDSM4(ah[mt][0], ah[mt][1], ah[mt][2], ah[mt][3], ab + mt * 2304);
                if (NA == 2)
                    LDSM4(al[mt][0], al[mt][1], al[mt][2], al[mt][3],
                          ab + TILE_B + mt * 2304);
            }
#pragma unroll
            for (int p = 0; p < 2; p++) {
                LDSM4(bh[2*p][0], bh[2*p][1], bh[2*p+1][0], bh[2*p+1][1],
                      bb + p * 2304);
                if (NB == 2)
                    LDSM4(bl[2*p][0], bl[2*p][1], bl[2*p+1][0], bl[2*p+1][1],
                          bb + TILE_B + p * 2304);
            }
#pragma unroll
            for (int mt = 0; mt < 4; mt++)
#pragma unroll
                for (int nt = 0; nt < 4; nt++)
                    mma16816(acc[mt][nt], ah[mt], bh[nt]);
            if (NA == 2) {
#pragma unroll
                for (int mt = 0; mt < 4; mt++)
#pragma unroll
                    for (int nt = 0; nt < 4; nt++)
                        mma16816(acc[mt][nt], al[mt], bh[nt]);
            }
            if (NB == 2) {
#pragma unroll
                for (int mt = 0; mt < 4; mt++)
#pragma unroll
                    for (int nt = 0; nt < 4; nt++)
                        mma16816(acc[mt][nt], ah[mt], bl[nt]);
            }
        }

        if (ch + 2 < nch) {
            __syncthreads();
            issue(ch + 2, ch & 1);
        }
    }

    // ---------------- epilogue -------------------------------------------------
    if (EPI <= 3 || EPI == 7 || EPI == 8) {
#pragma unroll
        for (int mt = 0; mt < 4; mt++)
#pragma unroll
            for (int nt = 0; nt < 4; nt++) {
                const int ri2 = wm + mt * 16 + gr;
                const int ci  = wn + nt * 8 + 2 * lc;
#pragma unroll
                for (int hf = 0; hf < 2; hf++) {
                    const int r = row0 + ri2 + hf * 8;
                    const int c = col0 + ci;
                    float v0 = acc[mt][nt][hf * 2 + 0];
                    float v1 = acc[mt][nt][hf * 2 + 1];
                    if (EPI == 2 || EPI == 7) { v0 = fmaxf(v0, 0.f); v1 = fmaxf(v1, 0.f); }
                    if (EPI == 3 || EPI == 8) {
                        float2 rv = *(const float2*)&R[(size_t)r * Ntot + c];
                        v0 += rv.x; v1 += rv.y;
                        *(float2*)&Cf[(size_t)r * ldC + c] = make_float2(v0, v1);
                    }
                    if (EPI == 0) {
                        *(float2*)&Cf[(size_t)r * ldC + c] = make_float2(v0, v1);
                    } else if (EPI == 7 || EPI == 8) {
                        *(__half2*)&Ch[(size_t)r * ldC + c] =
                            __halves2half2(__float2half_rn(v0), __float2half_rn(v1));
                    } else {
                        fp16 h0, l0, h1, l1;
                        split2(v0, h0, l0); split2(v1, h1, l1);
                        *(__half2*)&Ch[(size_t)r * ldC + c] = __halves2half2(h0, h1);
                        *(__half2*)&Cl[(size_t)r * ldC + c] = __halves2half2(l0, l1);
                    }
                }
            }
    } else {
        // transposed epilogues via fp32 smem buffer [128][130]
        __syncthreads();
        float* Tb = (float*)smem_raw;
#pragma unroll
        for (int mt = 0; mt < 4; mt++)
#pragma unroll
            for (int nt = 0; nt < 4; nt++) {
                const int ri2 = wm + mt * 16 + gr;
                const int ci  = wn + nt * 8 + 2 * lc;
#pragma unroll
                for (int hf = 0; hf < 2; hf++) {
                    const int rr = ri2 + hf * 8;
                    float v0 = acc[mt][nt][hf * 2 + 0];
                    float v1 = acc[mt][nt][hf * 2 + 1];
                    if (EPI == 5) {
                        float2 rv = *(const float2*)
                            &R[(size_t)(row0 + rr) * Ntot + col0 + ci];
                        v0 += rv.x; v1 += rv.y;
                    }
                    Tb[rr * 130 + ci]     = v0;
                    Tb[rr * 130 + ci + 1] = v1;
                }
            }
        __syncthreads();
        const int j  = tid & 127;          // output row within tile = GEMM col
        const int sg = tid >> 7;
        const int rb = sg * 64;
        if (EPI == 4 || EPI == 6) {
#pragma unroll
            for (int g = 0; g < 16; g++) {
                uint32_t hp[2], lp[2];
#pragma unroll
                for (int e = 0; e < 2; e++) {
                    float v0 = Tb[(rb + g * 4 + 2 * e)     * 130 + j];
                    float v1 = Tb[(rb + g * 4 + 2 * e + 1) * 130 + j];
                    fp16 h0, l0, h1, l1;
                    split2(v0, h0, l0); split2(v1, h1, l1);
                    __half2 hh = __halves2half2(h0, h1), ll = __halves2half2(l0, l1);
                    hp[e] = *(uint32_t*)&hh; lp[e] = *(uint32_t*)&ll;
                }
                size_t o = (size_t)(col0 + j) * ldC + row0 + rb + g * 4;
                *(uint2*)&Ch[o] = make_uint2(hp[0], hp[1]);
                if (EPI == 4)
                    *(uint2*)&Cl[o] = make_uint2(lp[0], lp[1]);
            }
        } else {  // EPI 5
#pragma unroll
            for (int g = 0; g < 16; g++) {
                float4 v;
                v.x = Tb[(rb + g * 4 + 0) * 130 + j];
                v.y = Tb[(rb + g * 4 + 1) * 130 + j];
                v.z = Tb[(rb + g * 4 + 2) * 130 + j];
                v.w = Tb[(rb + g * 4 + 3) * 130 + j];
                *(float4*)&Cf[(size_t)(col0 + j) * ldC + row0 + rb + g * 4] = v;
            }
        }
    }
}

// ---------------- transpose + fp16 split -------------------------------------
__global__ __launch_bounds__(256)
void tsplit(const float* __restrict__ in, fp16* __restrict__ oh,
            fp16* __restrict__ ol, float* __restrict__ of, int Rr, int Cc)
{
    __shared__ float t[32][33];
    int x = blockIdx.x * 32 + threadIdx.x;
    int y = blockIdx.y * 32 + threadIdx.y;
#pragma unroll
    for (int i = 0; i < 32; i += 8)
        t[threadIdx.y + i][threadIdx.x] = in[(size_t)(y + i) * Cc + x];
    __syncthreads();
    int xo = blockIdx.y * 32 + threadIdx.x;
    int yo = blockIdx.x * 32 + threadIdx.y;
#pragma unroll
    for (int i = 0; i < 32; i += 8) {
        float v = t[threadIdx.x][threadIdx.y + i];
        size_t o = (size_t)(yo + i) * Rr + xo;
        fp16 h, l; split2(v, h, l);
        oh[o] = h; if (ol) ol[o] = l;
        if (of) of[o] = v;
    }
}

// ---------------- straight fp16 split ----------------------------------------
__global__ __launch_bounds__(256)
void ssplit(const float* __restrict__ in, fp16* __restrict__ oh,
            fp16* __restrict__ ol, int n)
{
    int i = blockIdx.x * 256 + threadIdx.x;
    if (i < n) {
        fp16 h, l; split2(in[i], h, l);
        oh[i] = h; ol[i] = l;
    }
}

// ---------------- causal softmax -> fp16 A (hi only) -------------------------
__global__ __launch_bounds__(256)
void softmax_fp16(const float* __restrict__ S, fp16* __restrict__ Ah)
{
    const int row = blockIdx.x;
    const int len = row + 1;
    __shared__ float buf[NTOK];
    __shared__ float red[256];
    const int tid = threadIdx.x;
    const float* p = S + (size_t)row * NTOK;

    float m = NEG_INF;
    for (int j = tid; j < len; j += 256) { float v = p[j]; buf[j] = v; m = fmaxf(m, v); }
    red[tid] = m; __syncthreads();
    for (int s = 128; s > 0; s >>= 1) {
        if (tid < s) red[tid] = fmaxf(red[tid], red[tid + s]);
        __syncthreads();
    }
    m = red[0]; __syncthreads();

    float sum = 0.f;
    for (int j = tid; j < len; j += 256) { float e = __expf(buf[j] - m); buf[j] = e; sum += e; }
    red[tid] = sum; __syncthreads();
    for (int s = 128; s > 0; s >>= 1) {
        if (tid < s) red[tid] += red[tid + s];
        __syncthreads();
    }
    const float inv = 1.f / red[0];

    const int be = ((row >> 7) + 1) << 7;   // zero-fill to row-block end for CKLIM
    for (int j = tid; j < be; j += 256) {
        float v = (j < len) ? buf[j] * inv : 0.f;
        Ah[(size_t)row * NTOK + j] = __float2half_rn(v);
    }
}

// ---------------- driver ------------------------------------------------------
#define DS3 (2 * 4 * TILE_B)   // 147456
#define DS1 (2 * 2 * TILE_B)   //  73728 -> 2 CTAs/SM

extern "C" void kernel_launch(void* const* d_in, const int* in_sizes, int n_in,
                              void* d_out, int out_size) {
    (void)in_sizes; (void)n_in; (void)out_size;
    const float* X      = (const float*)d_in[0];
    const float* W_Q    = (const float*)d_in[1];
    const float* W_K    = (const float*)d_in[2];
    const float* W_V    = (const float*)d_in[3];
    const float* W_O    = (const float*)d_in[4];
    const float* mlp_in = (const float*)d_in[5];
    const float* mlp_out= (const float*)d_in[6];
    float* out = (float*)d_out;

    float *Xt, *S, *X2;
    fp16 *Xth, *Xtl, *PAh, *PAl, *PBh, *PBl, *POh, *POl;
    fp16 *W4h, *W5h, *Qmh, *Qml, *RHth, *RHtl;
    fp16 *Ah, *X2h, *Hh;
    cudaGetSymbolAddress((void**)&Xt,  g_Xt);   cudaGetSymbolAddress((void**)&Xth, g_Xth);
    cudaGetSymbolAddress((void**)&Xtl, g_Xtl);  cudaGetSymbolAddress((void**)&PAh, g_PAh);
    cudaGetSymbolAddress((void**)&PAl, g_PAl);  cudaGetSymbolAddress((void**)&PBh, g_PBh);
    cudaGetSymbolAddress((void**)&PBl, g_PBl);  cudaGetSymbolAddress((void**)&POh, g_POh);
    cudaGetSymbolAddress((void**)&POl, g_POl);  cudaGetSymbolAddress((void**)&W4h, g_W4h);
    cudaGetSymbolAddress((void**)&W5h, g_W5h);  cudaGetSymbolAddress((void**)&Qmh, g_Qmh);
    cudaGetSymbolAddress((void**)&Qml, g_Qml);  cudaGetSymbolAddress((void**)&RHth, g_RHth);
    cudaGetSymbolAddress((void**)&RHtl, g_RHtl); cudaGetSymbolAddress((void**)&S,  g_S);
    cudaGetSymbolAddress((void**)&Ah,  g_Ah);
    cudaGetSymbolAddress((void**)&X2,  g_X2);   cudaGetSymbolAddress((void**)&X2h, g_X2h);
    cudaGetSymbolAddress((void**)&Hh,  g_Hh);

    cudaFuncSetAttribute(gemm_mma<4,3,0,0,1>, cudaFuncAttributeMaxDynamicSharedMemorySize, DS3);
    cudaFuncSetAttribute(gemm_mma<1,3,0,0,1>, cudaFuncAttributeMaxDynamicSharedMemorySize, DS3);
    cudaFuncSetAttribute(gemm_mma<0,3,1,0,1>, cudaFuncAttributeMaxDynamicSharedMemorySize, DS3);
    cudaFuncSetAttribute(gemm_mma<6,1,0,0,2>, cudaFuncAttributeMaxDynamicSharedMemorySize, DS1);
    cudaFuncSetAttribute(gemm_mma<8,1,0,1,2>, cudaFuncAttributeMaxDynamicSharedMemorySize, DS1);
    cudaFuncSetAttribute(gemm_mma<7,1,0,0,2>, cudaFuncAttributeMaxDynamicSharedMemorySize, DS1);
    cudaFuncSetAttribute(gemm_mma<5,1,0,0,2>, cudaFuncAttributeMaxDynamicSharedMemorySize, DS1);

    const size_t WSZ = (size_t)DM * DM;
    dim3 tb(32, 8);
    dim3 gw(DM / 32, DM / 32);

    // preprocessing: transposes + splits
    tsplit<<<dim3(NTOK / 32, DM / 32), tb>>>(X, Xth, Xtl, Xt, DM, NTOK);
    ssplit<<<(int)(WSZ / 256), 256>>>(W_Q, PAh, PAl, (int)WSZ);            // A0 = Wq
    ssplit<<<(int)(WSZ / 256), 256>>>(W_V, PAh + WSZ, PAl + WSZ, (int)WSZ);// A1 = Wv
    ssplit<<<(int)(WSZ / 256), 256>>>(W_K, PBh, PBl, (int)WSZ);            // B0 = Wk
    tsplit<<<gw, tb>>>(W_O, PBh + WSZ, PBl + WSZ, nullptr, DM, DM);        // B1 = Wo^T
    tsplit<<<gw, tb>>>(mlp_in,  W4h, nullptr, nullptr, DM, DM);
    tsplit<<<gw, tb>>>(mlp_out, W5h, nullptr, nullptr, DM, DM);

    dim3 blk(256);
    dim3 grid_p(DM / 128, DM / 128, 2);    // z-batched preps: M^T and Wvo^T
    dim3 grid_d(DM / 128, NTOK / 128);
    dim3 grid_s(NTOK / 128, NTOK / 128);

    // preps (3-term): z=0: M = Wq@Wk^T -> M^T ; z=1: Wvo = Wv@Wo -> Wvo^T
    gemm_mma<4,3,0,0,1><<<grid_p, blk, DS3>>>(PAh, PAl, PBh, PBl,
                                              nullptr, nullptr, POh, POl, DM, DM, DM);
    // Qm = Xt @ M  (3-term)  [B = M^T]
    gemm_mma<1,3,0,0,1><<<grid_d, blk, DS3>>>(Xth, Xtl, POh, POl,
                                              nullptr, nullptr, Qmh, Qml, DM, DM, DM);
    // S = Qm @ Xt^T  (3-term, causal skip)
    gemm_mma<0,3,1,0,1><<<grid_s, blk, DS3>>>(Qmh, Qml, Xth, Xtl,
                                              nullptr, S, nullptr, nullptr, NTOK, DM, NTOK);
    // softmax rows -> A fp16 hi (zero-filled to 128-block end)
    softmax_fp16<<<NTOK, 256>>>(S, Ah);
    // RH = Xth @ Wvo_h  (1-term) -> RH^T hi only
    gemm_mma<6,1,0,0,2><<<grid_d, blk, DS1>>>(Xth, nullptr, POh + WSZ, nullptr,
                                              nullptr, nullptr, RHth, RHtl, DM, DM, NTOK);
    // X2 = Xt + A @ RH  (1-term, K bounded by causality) -> fp32 + hi
    gemm_mma<8,1,0,1,2><<<grid_d, blk, DS1>>>(Ah, nullptr, RHth, nullptr,
                                              Xt, X2, X2h, nullptr, DM, NTOK, DM);
    // H = relu(X2h @ mlp_in_h)  (1-term) -> hi only
    gemm_mma<7,1,0,0,2><<<grid_d, blk, DS1>>>(X2h, nullptr, W4h, nullptr,
                                              nullptr, nullptr, Hh, nullptr, DM, DM, DM);
    // out = (X2 + Hh @ mlp_out_h)^T  (1-term)
    gemm_mma<5,1,0,0,2><<<grid_d, blk, DS1>>>(Hh, nullptr, W5h, nullptr,
                                              X2, out, nullptr, nullptr, DM, DM, NTOK);
}

// round 16
// speedup vs baseline: 1.4822x; 1.4822x over previous
#include <cuda_runtime.h>
#include <cuda_fp16.h>
#include <cstdint>
#include <cstddef>

#define DM   1024
#define NTOK 4096

typedef __half fp16;

// ---------------- scratch ----------------------------------------------------
__device__ float g_Xt [(size_t)NTOK * DM];          // X^T fp32 (residual)
__device__ fp16  g_Xth[(size_t)NTOK * DM];
__device__ fp16  g_Xtl[(size_t)NTOK * DM];
__device__ fp16  g_PAh[(size_t)2 * DM * DM];        // [Wq ; Wv]  straight split hi
__device__ fp16  g_PAl[(size_t)2 * DM * DM];
__device__ fp16  g_PBh[(size_t)2 * DM * DM];        // [Wk ; Wo^T] hi
__device__ fp16  g_PBl[(size_t)2 * DM * DM];
__device__ fp16  g_POh[(size_t)2 * DM * DM];        // [M^T ; Wvo^T] hi
__device__ fp16  g_POl[(size_t)2 * DM * DM];
__device__ fp16  g_W4h[(size_t)DM * DM];            // mlp_in^T hi
__device__ fp16  g_W5h[(size_t)DM * DM];            // mlp_out^T hi
__device__ fp16  g_Qmh[(size_t)NTOK * DM];          // Xt @ M
__device__ fp16  g_Qml[(size_t)NTOK * DM];
__device__ fp16  g_RHth[(size_t)DM * NTOK];         // (Xt Wvo)^T  [dm][tok]
__device__ fp16  g_RHtl[(size_t)DM * NTOK];         // (unused; kept for layout)
__device__ float g_S  [(size_t)NTOK * NTOK];        // raw scores fp32
__device__ fp16  g_Ah [(size_t)NTOK * NTOK];        // softmax weights, fp16 hi only
__device__ float g_X2 [(size_t)NTOK * DM];          // fp32 (residual)
__device__ fp16  g_X2h[(size_t)NTOK * DM];
__device__ fp16  g_X2l[(size_t)NTOK * DM];
__device__ fp16  g_Hh [(size_t)NTOK * DM];

#define NEG_INF (-__int_as_float(0x7f800000))

// ---------------- small helpers ----------------------------------------------
__device__ __forceinline__ uint32_t smem_u32(const void* p) {
    uint32_t a;
    asm("{ .reg .u64 t; cvta.to.shared.u64 t, %1; cvt.u32.u64 %0, t; }"
        : "=r"(a) : "l"(p));
    return a;
}

#define CP16(d, p) \
    asm volatile("cp.async.cg.shared.global [%0], [%1], 16;" :: "r"(d), "l"(p) : "memory")
#define CP_COMMIT()  asm volatile("cp.async.commit_group;" ::: "memory")
#define CP_WAIT1()   asm volatile("cp.async.wait_group 1;" ::: "memory")
#define CP_WAIT0()   asm volatile("cp.async.wait_group 0;" ::: "memory")

#define LDSM4(r0, r1, r2, r3, addr) \
    asm volatile("ldmatrix.sync.aligned.m8n8.x4.shared.b16 {%0,%1,%2,%3}, [%4];" \
        : "=r"(r0), "=r"(r1), "=r"(r2), "=r"(r3) : "r"(addr))

__device__ __forceinline__ void mma16816(float* c, const uint32_t* a, const uint32_t* b) {
    asm volatile(
        "mma.sync.aligned.m16n8k16.row.col.f32.f16.f16.f32 "
        "{%0,%1,%2,%3}, {%4,%5,%6,%7}, {%8,%9}, {%0,%1,%2,%3};"
        : "+f"(c[0]), "+f"(c[1]), "+f"(c[2]), "+f"(c[3])
        : "r"(a[0]), "r"(a[1]), "r"(a[2]), "r"(a[3]), "r"(b[0]), "r"(b[1]));
}

__device__ __forceinline__ void split2(float v, fp16& h, fp16& l) {
    h = __float2half_rn(v);
    l = __float2half_rn(v - __half2float(h));
}

// ---------------- fp16-split GEMM (mma.sync + ldmatrix, 2-stage cp.async) ----
// C[M, Ntot] = A'[M,Ktot] @ B'[Ntot,Ktot]^T
//   TERMS=1: Ah·Bh            TERMS=2: (Ah+Al)·Bh        TERMS=3: +Ah·Bl
// CTA tile 128x128, warp tile 64x32, K-chunk 64.
// EPI: 0  Cf = acc (fp32)
//      1  Ch/Cl = split(acc)
//      3  Cf = acc + R ; Ch/Cl = split(Cf)
//      4  transposed: Ch/Cl[c*ldC + r] = split(acc)
//      5  transposed: Cf[c*ldC + r] = acc + R
//      6  transposed: Ch[c*ldC + r] = half(acc)   (hi only)
//      7  Ch = half(relu(acc))                    (hi only)
// CMASK: skip CTA tiles fully above causal diagonal
// CKLIM: K-loop bounded to row0+128 (A rows have zeros beyond)
// MINB:  min blocks per SM
// z-batch: blockIdx.z offsets A/B/Ch/Cl pointers by z*DM*DM (for fused preps)

#define TILE_B   18432               // 128 rows * 144B (64 fp16 = 128B + 16B pad)

template<int EPI, int TERMS, int CMASK, int CKLIM, int MINB>
__global__ void __launch_bounds__(256, MINB)
gemm_mma(const fp16* __restrict__ Ahp, const fp16* __restrict__ Alp,
         const fp16* __restrict__ Bhp, const fp16* __restrict__ Blp,
         const float* __restrict__ R,
         float* __restrict__ Cf, fp16* __restrict__ Ch, fp16* __restrict__ Cl,
         int Ntot, int Ktot, int ldC)
{
    constexpr int NA  = (TERMS >= 2) ? 2 : 1;      // A tiles (hi, lo?)
    constexpr int NB  = (TERMS == 3) ? 2 : 1;      // B tiles (hi, lo?)
    constexpr int STB = (NA + NB) * TILE_B;        // stage bytes
    constexpr int BOFF = NA * TILE_B;              // B hi offset within stage

    const int row0 = blockIdx.y * 128;
    const int col0 = blockIdx.x * 128;
    if (CMASK && col0 > row0 + 127) return;

    const size_t zo = (size_t)blockIdx.z * ((size_t)DM * DM);
    Ahp += zo; Bhp += zo; Ch += zo; Cl += zo;
    if (NA == 2) Alp += zo;
    if (NB == 2) Blp += zo;

    extern __shared__ __align__(16) char smem_raw[];
    const uint32_t sbase = smem_u32(smem_raw);

    const int tid  = threadIdx.x;
    const int lane = tid & 31;
    const int wid  = tid >> 5;
    const int wm   = (wid & 1) * 64;
    const int wn   = (wid >> 1) * 32;
    const int gr   = lane >> 2;
    const int lc   = lane & 3;

    // ldmatrix per-lane address components
    const int mi = lane >> 3, ri = lane & 7;
    const uint32_t aoff = (uint32_t)(((mi & 1) * 8 + ri) * 144 + (mi >> 1) * 16);
    const uint32_t boff = (uint32_t)(((mi >> 1) * 8 + ri) * 144 + (mi & 1) * 16);

    int nch = Ktot >> 6;
    if (CKLIM) { int lim = (row0 + 128) >> 6; nch = (lim < nch) ? lim : nch; }

    float acc[4][4][4] = {};

    // ---- loader: one 64-wide K chunk into stage stg ----
    const int ldr  = tid >> 1;        // 0..127 row
    const int lhf  = tid & 1;         // half-row (64B = 4 x 16B)
    auto issue = [&](int ch, int stg) {
        const size_t ko = (size_t)(ch << 6) + (lhf << 5);
        uint32_t dst = sbase + stg * STB + ldr * 144 + lhf * 64;
        const fp16* s0 = Ahp + (size_t)(row0 + ldr) * Ktot + ko;
        const fp16* s2 = Bhp + (size_t)(col0 + ldr) * Ktot + ko;
#pragma unroll
        for (int i = 0; i < 4; i++) CP16(dst + i * 16,          s0 + i * 8);
        if (NA == 2) {
            const fp16* s1 = Alp + (size_t)(row0 + ldr) * Ktot + ko;
#pragma unroll
            for (int i = 0; i < 4; i++) CP16(dst + TILE_B + i * 16, s1 + i * 8);
        }
#pragma unroll
        for (int i = 0; i < 4; i++) CP16(dst + BOFF + i * 16,   s2 + i * 8);
        if (NB == 2) {
            const fp16* s3 = Blp + (size_t)(col0 + ldr) * Ktot + ko;
#pragma unroll
            for (int i = 0; i < 4; i++) CP16(dst + BOFF + TILE_B + i * 16, s3 + i * 8);
        }
        CP_COMMIT();
    };

    issue(0, 0);
    if (nch > 1) issue(1, 1);

    for (int ch = 0; ch < nch; ch++) {
        if (ch + 1 < nch) CP_WAIT1(); else CP_WAIT0();
        __syncthreads();

        const uint32_t stq = sbase + (ch & 1) * STB;
        const uint32_t Abase = stq + wm * 144 + aoff;            // Ah
        const uint32_t Bbase = stq + BOFF + wn * 144 + boff;     // Bh

#pragma unroll
        for (int ks = 0; ks < 4; ks++) {
            const uint32_t ab = Abase + ks * 32;
            const uint32_t bb = Bbase + ks * 32;
            uint32_t ah[4][4], al[4][4], bh[4][2], bl[4][2];
#pragma unroll
            for (int mt = 0; mt < 4; mt++) {
                LDSM4(ah[mt][0], ah[mt][1], ah[mt][2], ah[mt][3], ab + mt * 2304);
                if (NA == 2)
                    LDSM4(al[mt][0], al[mt][1], al[mt][2], al[mt][3],
                          ab + TILE_B + mt * 2304);
            }
#pragma unroll
            for (int p = 0; p < 2; p++) {
                LDSM4(bh[2*p][0], bh[2*p][1], bh[2*p+1][0], bh[2*p+1][1],
                      bb + p * 2304);
                if (NB == 2)
                    LDSM4(bl[2*p][0], bl[2*p][1], bl[2*p+1][0], bl[2*p+1][1],
                          bb + TILE_B + p * 2304);
            }
#pragma unroll
            for (int mt = 0; mt < 4; mt++)
#pragma unroll
                for (int nt = 0; nt < 4; nt++)
                    mma16816(acc[mt][nt], ah[mt], bh[nt]);
            if (NA == 2) {
#pragma unroll
                for (int mt = 0; mt < 4; mt++)
#pragma unroll
                    for (int nt = 0; nt < 4; nt++)
                        mma16816(acc[mt][nt], al[mt], bh[nt]);
            }
            if (NB == 2) {
#pragma unroll
                for (int mt = 0; mt < 4; mt++)
#pragma unroll
                    for (int nt = 0; nt < 4; nt++)
                        mma16816(acc[mt][nt], ah[mt], bl[nt]);
            }
        }

        if (ch + 2 < nch) {
            __syncthreads();
            issue(ch + 2, ch & 1);
        }
    }

    // ---------------- epilogue -------------------------------------------------
    if (EPI <= 3 || EPI == 7) {
#pragma unroll
        for (int mt = 0; mt < 4; mt++)
#pragma unroll
            for (int nt = 0; nt < 4; nt++) {
                const int ri2 = wm + mt * 16 + gr;
                const int ci  = wn + nt * 8 + 2 * lc;
#pragma unroll
                for (int hf = 0; hf < 2; hf++) {
                    const int r = row0 + ri2 + hf * 8;
                    const int c = col0 + ci;
                    float v0 = acc[mt][nt][hf * 2 + 0];
                    float v1 = acc[mt][nt][hf * 2 + 1];
                    if (EPI == 7) { v0 = fmaxf(v0, 0.f); v1 = fmaxf(v1, 0.f); }
                    if (EPI == 3) {
                        float2 rv = *(const float2*)&R[(size_t)r * Ntot + c];
                        v0 += rv.x; v1 += rv.y;
                        *(float2*)&Cf[(size_t)r * ldC + c] = make_float2(v0, v1);
                    }
                    if (EPI == 0) {
                        *(float2*)&Cf[(size_t)r * ldC + c] = make_float2(v0, v1);
                    } else if (EPI == 7) {
                        *(__half2*)&Ch[(size_t)r * ldC + c] =
                            __halves2half2(__float2half_rn(v0), __float2half_rn(v1));
                    } else {
                        fp16 h0, l0, h1, l1;
                        split2(v0, h0, l0); split2(v1, h1, l1);
                        *(__half2*)&Ch[(size_t)r * ldC + c] = __halves2half2(h0, h1);
                        *(__half2*)&Cl[(size_t)r * ldC + c] = __halves2half2(l0, l1);
                    }
                }
            }
    } else {
        // transposed epilogues via fp32 smem buffer [128][130]
        __syncthreads();
        float* Tb = (float*)smem_raw;
#pragma unroll
        for (int mt = 0; mt < 4; mt++)
#pragma unroll
            for (int nt = 0; nt < 4; nt++) {
                const int ri2 = wm + mt * 16 + gr;
                const int ci  = wn + nt * 8 + 2 * lc;
#pragma unroll
                for (int hf = 0; hf < 2; hf++) {
                    const int rr = ri2 + hf * 8;
                    float v0 = acc[mt][nt][hf * 2 + 0];
                    float v1 = acc[mt][nt][hf * 2 + 1];
                    if (EPI == 5) {
                        float2 rv = *(const float2*)
                            &R[(size_t)(row0 + rr) * Ntot + col0 + ci];
                        v0 += rv.x; v1 += rv.y;
                    }
                    Tb[rr * 130 + ci]     = v0;
                    Tb[rr * 130 + ci + 1] = v1;
                }
            }
        __syncthreads();
        const int j  = tid & 127;          // output row within tile = GEMM col
        const int sg = tid >> 7;
        const int rb = sg * 64;
        if (EPI == 4 || EPI == 6) {
#pragma unroll
            for (int g = 0; g < 16; g++) {
                uint32_t hp[2], lp[2];
#pragma unroll
                for (int e = 0; e < 2; e++) {
                    float v0 = Tb[(rb + g * 4 + 2 * e)     * 130 + j];
                    float v1 = Tb[(rb + g * 4 + 2 * e + 1) * 130 + j];
                    fp16 h0, l0, h1, l1;
                    split2(v0, h0, l0); split2(v1, h1, l1);
                    __half2 hh = __halves2half2(h0, h1), ll = __halves2half2(l0, l1);
                    hp[e] = *(uint32_t*)&hh; lp[e] = *(uint32_t*)&ll;
                }
                size_t o = (size_t)(col0 + j) * ldC + row0 + rb + g * 4;
                *(uint2*)&Ch[o] = make_uint2(hp[0], hp[1]);
                if (EPI == 4)
                    *(uint2*)&Cl[o] = make_uint2(lp[0], lp[1]);
            }
        } else {  // EPI 5
#pragma unroll
            for (int g = 0; g < 16; g++) {
                float4 v;
                v.x = Tb[(rb + g * 4 + 0) * 130 + j];
                v.y = Tb[(rb + g * 4 + 1) * 130 + j];
                v.z = Tb[(rb + g * 4 + 2) * 130 + j];
                v.w = Tb[(rb + g * 4 + 3) * 130 + j];
                *(float4*)&Cf[(size_t)(col0 + j) * ldC + row0 + rb + g * 4] = v;
            }
        }
    }
}

// ---------------- transpose + fp16 split -------------------------------------
__global__ __launch_bounds__(256)
void tsplit(const float* __restrict__ in, fp16* __restrict__ oh,
            fp16* __restrict__ ol, float* __restrict__ of, int Rr, int Cc)
{
    __shared__ float t[32][33];
    int x = blockIdx.x * 32 + threadIdx.x;
    int y = blockIdx.y * 32 + threadIdx.y;
#pragma unroll
    for (int i = 0; i < 32; i += 8)
        t[threadIdx.y + i][threadIdx.x] = in[(size_t)(y + i) * Cc + x];
    __syncthreads();
    int xo = blockIdx.y * 32 + threadIdx.x;
    int yo = blockIdx.x * 32 + threadIdx.y;
#pragma unroll
    for (int i = 0; i < 32; i += 8) {
        float v = t[threadIdx.x][threadIdx.y + i];
        size_t o = (size_t)(yo + i) * Rr + xo;
        fp16 h, l; split2(v, h, l);
        oh[o] = h; if (ol) ol[o] = l;
        if (of) of[o] = v;
    }
}

// ---------------- straight fp16 split ----------------------------------------
__global__ __launch_bounds__(256)
void ssplit(const float* __restrict__ in, fp16* __restrict__ oh,
            fp16* __restrict__ ol, int n)
{
    int i = blockIdx.x * 256 + threadIdx.x;
    if (i < n) {
        fp16 h, l; split2(in[i], h, l);
        oh[i] = h; ol[i] = l;
    }
}

// ---------------- causal softmax -> fp16 A (hi only) -------------------------
__global__ __launch_bounds__(256)
void softmax_fp16(const float* __restrict__ S, fp16* __restrict__ Ah)
{
    const int row = blockIdx.x;
    const int len = row + 1;
    __shared__ float buf[NTOK];
    __shared__ float red[256];
    const int tid = threadIdx.x;
    const float* p = S + (size_t)row * NTOK;

    float m = NEG_INF;
    for (int j = tid; j < len; j += 256) { float v = p[j]; buf[j] = v; m = fmaxf(m, v); }
    red[tid] = m; __syncthreads();
    for (int s = 128; s > 0; s >>= 1) {
        if (tid < s) red[tid] = fmaxf(red[tid], red[tid + s]);
        __syncthreads();
    }
    m = red[0]; __syncthreads();

    float sum = 0.f;
    for (int j = tid; j < len; j += 256) { float e = __expf(buf[j] - m); buf[j] = e; sum += e; }
    red[tid] = sum; __syncthreads();
    for (int s = 128; s > 0; s >>= 1) {
        if (tid < s) red[tid] += red[tid + s];
        __syncthreads();
    }
    const float inv = 1.f / red[0];

    const int be = ((row >> 7) + 1) << 7;   // zero-fill to row-block end for CKLIM
    for (int j = tid; j < be; j += 256) {
        float v = (j < len) ? buf[j] * inv : 0.f;
        Ah[(size_t)row * NTOK + j] = __float2half_rn(v);
    }
}

// ---------------- driver ------------------------------------------------------
#define DS3 (2 * 4 * TILE_B)   // 147456
#define DS2 (2 * 3 * TILE_B)   // 110592 -> 2 CTAs/SM
#define DS1 (2 * 2 * TILE_B)   //  73728 -> 2 CTAs/SM

extern "C" void kernel_launch(void* const* d_in, const int* in_sizes, int n_in,
                              void* d_out, int out_size) {
    (void)in_sizes; (void)n_in; (void)out_size;
    const float* X      = (const float*)d_in[0];
    const float* W_Q    = (const float*)d_in[1];
    const float* W_K    = (const float*)d_in[2];
    const float* W_V    = (const float*)d_in[3];
    const float* W_O    = (const float*)d_in[4];
    const float* mlp_in = (const float*)d_in[5];
    const float* mlp_out= (const float*)d_in[6];
    float* out = (float*)d_out;

    float *Xt, *S, *X2;
    fp16 *Xth, *Xtl, *PAh, *PAl, *PBh, *PBl, *POh, *POl;
    fp16 *W4h, *W5h, *Qmh, *Qml, *RHth, *RHtl;
    fp16 *Ah, *X2h, *X2l, *Hh;
    cudaGetSymbolAddress((void**)&Xt,  g_Xt);   cudaGetSymbolAddress((void**)&Xth, g_Xth);
    cudaGetSymbolAddress((void**)&Xtl, g_Xtl);  cudaGetSymbolAddress((void**)&PAh, g_PAh);
    cudaGetSymbolAddress((void**)&PAl, g_PAl);  cudaGetSymbolAddress((void**)&PBh, g_PBh);
    cudaGetSymbolAddress((void**)&PBl, g_PBl);  cudaGetSymbolAddress((void**)&POh, g_POh);
    cudaGetSymbolAddress((void**)&POl, g_POl);  cudaGetSymbolAddress((void**)&W4h, g_W4h);
    cudaGetSymbolAddress((void**)&W5h, g_W5h);  cudaGetSymbolAddress((void**)&Qmh, g_Qmh);
    cudaGetSymbolAddress((void**)&Qml, g_Qml);  cudaGetSymbolAddress((void**)&RHth, g_RHth);
    cudaGetSymbolAddress((void**)&RHtl, g_RHtl); cudaGetSymbolAddress((void**)&S,  g_S);
    cudaGetSymbolAddress((void**)&Ah,  g_Ah);
    cudaGetSymbolAddress((void**)&X2,  g_X2);   cudaGetSymbolAddress((void**)&X2h, g_X2h);
    cudaGetSymbolAddress((void**)&X2l, g_X2l);  cudaGetSymbolAddress((void**)&Hh,  g_Hh);

    cudaFuncSetAttribute(gemm_mma<4,3,0,0,1>, cudaFuncAttributeMaxDynamicSharedMemorySize, DS3);
    cudaFuncSetAttribute(gemm_mma<1,3,0,0,1>, cudaFuncAttributeMaxDynamicSharedMemorySize, DS3);
    cudaFuncSetAttribute(gemm_mma<0,3,1,0,1>, cudaFuncAttributeMaxDynamicSharedMemorySize, DS3);
    cudaFuncSetAttribute(gemm_mma<6,1,0,0,2>, cudaFuncAttributeMaxDynamicSharedMemorySize, DS1);
    cudaFuncSetAttribute(gemm_mma<3,1,0,1,2>, cudaFuncAttributeMaxDynamicSharedMemorySize, DS1);
    cudaFuncSetAttribute(gemm_mma<7,2,0,0,2>, cudaFuncAttributeMaxDynamicSharedMemorySize, DS2);
    cudaFuncSetAttribute(gemm_mma<5,1,0,0,2>, cudaFuncAttributeMaxDynamicSharedMemorySize, DS1);

    const size_t WSZ = (size_t)DM * DM;
    dim3 tb(32, 8);
    dim3 gw(DM / 32, DM / 32);

    // preprocessing: transposes + splits
    tsplit<<<dim3(NTOK / 32, DM / 32), tb>>>(X, Xth, Xtl, Xt, DM, NTOK);
    ssplit<<<(int)(WSZ / 256), 256>>>(W_Q, PAh, PAl, (int)WSZ);            // A0 = Wq
    ssplit<<<(int)(WSZ / 256), 256>>>(W_V, PAh + WSZ, PAl + WSZ, (int)WSZ);// A1 = Wv
    ssplit<<<(int)(WSZ / 256), 256>>>(W_K, PBh, PBl, (int)WSZ);            // B0 = Wk
    tsplit<<<gw, tb>>>(W_O, PBh + WSZ, PBl + WSZ, nullptr, DM, DM);        // B1 = Wo^T
    tsplit<<<gw, tb>>>(mlp_in,  W4h, nullptr, nullptr, DM, DM);
    tsplit<<<gw, tb>>>(mlp_out, W5h, nullptr, nullptr, DM, DM);

    dim3 blk(256);
    dim3 grid_p(DM / 128, DM / 128, 2);    // z-batched preps: M^T and Wvo^T
    dim3 grid_d(DM / 128, NTOK / 128);
    dim3 grid_s(NTOK / 128, NTOK / 128);

    // preps (3-term): z=0: M = Wq@Wk^T -> M^T ; z=1: Wvo = Wv@Wo -> Wvo^T
    gemm_mma<4,3,0,0,1><<<grid_p, blk, DS3>>>(PAh, PAl, PBh, PBl,
                                              nullptr, nullptr, POh, POl, DM, DM, DM);
    // Qm = Xt @ M  (3-term)  [B = M^T]
    gemm_mma<1,3,0,0,1><<<grid_d, blk, DS3>>>(Xth, Xtl, POh, POl,
                                              nullptr, nullptr, Qmh, Qml, DM, DM, DM);
    // S = Qm @ Xt^T  (3-term, causal skip)
    gemm_mma<0,3,1,0,1><<<grid_s, blk, DS3>>>(Qmh, Qml, Xth, Xtl,
                                              nullptr, S, nullptr, nullptr, NTOK, DM, NTOK);
    // softmax rows -> A fp16 hi (zero-filled to 128-block end)
    softmax_fp16<<<NTOK, 256>>>(S, Ah);
    // RH = Xth @ Wvo_h  (1-term) -> RH^T hi only
    gemm_mma<6,1,0,0,2><<<grid_d, blk, DS1>>>(Xth, nullptr, POh + WSZ, nullptr,
                                              nullptr, nullptr, RHth, RHtl, DM, DM, NTOK);
    // X2 = Xt + A @ RH  (1-term, K bounded by causality) -> fp32 + hi/lo
    gemm_mma<3,1,0,1,2><<<grid_d, blk, DS1>>>(Ah, nullptr, RHth, nullptr,
                                              Xt, X2, X2h, X2l, DM, NTOK, DM);
    // H = relu((X2h+X2l) @ mlp_in_h)  (2-term) -> hi only
    gemm_mma<7,2,0,0,2><<<grid_d, blk, DS2>>>(X2h, X2l, W4h, nullptr,
                                              nullptr, nullptr, Hh, nullptr, DM, DM, DM);
    // out = (X2 + Hh @ mlp_out_h)^T  (1-term)
    gemm_mma<5,1,0,0,2><<<grid_d, blk, DS1>>>(Hh, nullptr, W5h, nullptr,
                                              X2, out, nullptr, nullptr, DM, DM, NTOK);
}

// round 17
// speedup vs baseline: 1.5321x; 1.0337x over previous
#include <cuda_runtime.h>
#include <cuda_fp16.h>
#include <cstdint>
#include <cstddef>

#define DM   1024
#define NTOK 4096

typedef __half fp16;

// ---------------- scratch ----------------------------------------------------
__device__ float g_Xt [(size_t)NTOK * DM];          // X^T fp32 (residual)
__device__ fp16  g_Xth[(size_t)NTOK * DM];
__device__ fp16  g_Xtl[(size_t)NTOK * DM];
__device__ fp16  g_PAh[(size_t)2 * DM * DM];        // [Wq ; Wv]  straight split hi
__device__ fp16  g_PAl[(size_t)2 * DM * DM];
__device__ fp16  g_PBh[(size_t)2 * DM * DM];        // [Wk ; Wo^T] hi
__device__ fp16  g_PBl[(size_t)2 * DM * DM];
__device__ fp16  g_POh[(size_t)2 * DM * DM];        // [M^T ; Wvo^T] hi
__device__ fp16  g_POl[(size_t)2 * DM * DM];
__device__ fp16  g_W4h[(size_t)DM * DM];            // mlp_in^T hi
__device__ fp16  g_W5h[(size_t)DM * DM];            // mlp_out^T hi
__device__ fp16  g_Qmh[(size_t)NTOK * DM];          // Xt @ M
__device__ fp16  g_Qml[(size_t)NTOK * DM];
__device__ fp16  g_RHth[(size_t)DM * NTOK];         // (Xt Wvo)^T  [dm][tok]
__device__ fp16  g_RHtl[(size_t)DM * NTOK];         // (unused; kept for layout)
__device__ float g_S  [(size_t)NTOK * NTOK];        // raw scores fp32
__device__ fp16  g_Ah [(size_t)NTOK * NTOK];        // softmax weights, fp16 hi only
__device__ float g_X2 [(size_t)NTOK * DM];          // fp32 (residual)
__device__ fp16  g_X2h[(size_t)NTOK * DM];
__device__ fp16  g_Hh [(size_t)NTOK * DM];

#define NEG_INF (-__int_as_float(0x7f800000))

// ---------------- small helpers ----------------------------------------------
__device__ __forceinline__ uint32_t smem_u32(const void* p) {
    uint32_t a;
    asm("{ .reg .u64 t; cvta.to.shared.u64 t, %1; cvt.u32.u64 %0, t; }"
        : "=r"(a) : "l"(p));
    return a;
}

#define CP16(d, p) \
    asm volatile("cp.async.cg.shared.global [%0], [%1], 16;" :: "r"(d), "l"(p) : "memory")
#define CP_COMMIT()  asm volatile("cp.async.commit_group;" ::: "memory")
#define CP_WAIT1()   asm volatile("cp.async.wait_group 1;" ::: "memory")
#define CP_WAIT0()   asm volatile("cp.async.wait_group 0;" ::: "memory")

#define LDSM4(r0, r1, r2, r3, addr) \
    asm volatile("ldmatrix.sync.aligned.m8n8.x4.shared.b16 {%0,%1,%2,%3}, [%4];" \
        : "=r"(r0), "=r"(r1), "=r"(r2), "=r"(r3) : "r"(addr))

__device__ __forceinline__ void mma16816(float* c, const uint32_t* a, const uint32_t* b) {
    asm volatile(
        "mma.sync.aligned.m16n8k16.row.col.f32.f16.f16.f32 "
        "{%0,%1,%2,%3}, {%4,%5,%6,%7}, {%8,%9}, {%0,%1,%2,%3};"
        : "+f"(c[0]), "+f"(c[1]), "+f"(c[2]), "+f"(c[3])
        : "r"(a[0]), "r"(a[1]), "r"(a[2]), "r"(a[3]), "r"(b[0]), "r"(b[1]));
}

__device__ __forceinline__ void split2(float v, fp16& h, fp16& l) {
    h = __float2half_rn(v);
    l = __float2half_rn(v - __half2float(h));
}

// ---------------- fp16-split GEMM (mma.sync + ldmatrix, 2-stage cp.async) ----
// C[M, Ntot] = A'[M,Ktot] @ B'[Ntot,Ktot]^T
//   TERMS=1: Ah·Bh            TERMS=2: (Ah+Al)·Bh        TERMS=3: +Ah·Bl
// CTA tile 128x128, warp tile 64x32, K-chunk 64.
// EPI: 0  Cf = acc (fp32)
//      1  Ch/Cl = split(acc)
//      3  Cf = acc + R ; Ch/Cl = split(Cf)
//      4  transposed: Ch/Cl[c*ldC + r] = split(acc)
//      5  transposed: Cf[c*ldC + r] = acc + R
//      6  transposed: Ch[c*ldC + r] = half(acc)   (hi only)
//      7  Ch = half(relu(acc))                    (hi only)
//      8  Cf = acc + R ; Ch = half(Cf)            (hi only)
// CMASK: skip CTA tiles fully above causal diagonal
// CKLIM: K-loop bounded to row0+128 (A rows have zeros beyond)
// MINB:  min blocks per SM
// z-batch: blockIdx.z offsets A/B/Ch/Cl pointers by z*DM*DM (for fused preps)

#define TILE_B   18432               // 128 rows * 144B (64 fp16 = 128B + 16B pad)

template<int EPI, int TERMS, int CMASK, int CKLIM, int MINB>
__global__ void __launch_bounds__(256, MINB)
gemm_mma(const fp16* __restrict__ Ahp, const fp16* __restrict__ Alp,
         const fp16* __restrict__ Bhp, const fp16* __restrict__ Blp,
         const float* __restrict__ R,
         float* __restrict__ Cf, fp16* __restrict__ Ch, fp16* __restrict__ Cl,
         int Ntot, int Ktot, int ldC)
{
    constexpr int NA  = (TERMS >= 2) ? 2 : 1;      // A tiles (hi, lo?)
    constexpr int NB  = (TERMS == 3) ? 2 : 1;      // B tiles (hi, lo?)
    constexpr int STB = (NA + NB) * TILE_B;        // stage bytes
    constexpr int BOFF = NA * TILE_B;              // B hi offset within stage

    const int row0 = blockIdx.y * 128;
    const int col0 = blockIdx.x * 128;
    if (CMASK && col0 > row0 + 127) return;

    const size_t zo = (size_t)blockIdx.z * ((size_t)DM * DM);
    Ahp += zo; Bhp += zo; Ch += zo; Cl += zo;
    if (NA == 2) Alp += zo;
    if (NB == 2) Blp += zo;

    extern __shared__ __align__(16) char smem_raw[];
    const uint32_t sbase = smem_u32(smem_raw);

    const int tid  = threadIdx.x;
    const int lane = tid & 31;
    const int wid  = tid >> 5;
    const int wm   = (wid & 1) * 64;
    const int wn   = (wid >> 1) * 32;
    const int gr   = lane >> 2;
    const int lc   = lane & 3;

    // ldmatrix per-lane address components
    const int mi = lane >> 3, ri = lane & 7;
    const uint32_t aoff = (uint32_t)(((mi & 1) * 8 + ri) * 144 + (mi >> 1) * 16);
    const uint32_t boff = (uint32_t)(((mi >> 1) * 8 + ri) * 144 + (mi & 1) * 16);

    int nch = Ktot >> 6;
    if (CKLIM) { int lim = (row0 + 128) >> 6; nch = (lim < nch) ? lim : nch; }

    float acc[4][4][4] = {};

    // ---- loader: one 64-wide K chunk into stage stg ----
    const int ldr  = tid >> 1;        // 0..127 row
    const int lhf  = tid & 1;         // half-row (64B = 4 x 16B)
    auto issue = [&](int ch, int stg) {
        const size_t ko = (size_t)(ch << 6) + (lhf << 5);
        uint32_t dst = sbase + stg * STB + ldr * 144 + lhf * 64;
        const fp16* s0 = Ahp + (size_t)(row0 + ldr) * Ktot + ko;
        const fp16* s2 = Bhp + (size_t)(col0 + ldr) * Ktot + ko;
#pragma unroll
        for (int i = 0; i < 4; i++) CP16(dst + i * 16,          s0 + i * 8);
        if (NA == 2) {
            const fp16* s1 = Alp + (size_t)(row0 + ldr) * Ktot + ko;
#pragma unroll
            for (int i = 0; i < 4; i++) CP16(dst + TILE_B + i * 16, s1 + i * 8);
        }
#pragma unroll
        for (int i = 0; i < 4; i++) CP16(dst + BOFF + i * 16,   s2 + i * 8);
        if (NB == 2) {
            const fp16* s3 = Blp + (size_t)(col0 + ldr) * Ktot + ko;
#pragma unroll
            for (int i = 0; i < 4; i++) CP16(dst + BOFF + TILE_B + i * 16, s3 + i * 8);
        }
        CP_COMMIT();
    };

    issue(0, 0);
    if (nch > 1) issue(1, 1);

    for (int ch = 0; ch < nch; ch++) {
        if (ch + 1 < nch) CP_WAIT1(); else CP_WAIT0();
        __syncthreads();

        const uint32_t stq = sbase + (ch & 1) * STB;
        const uint32_t Abase = stq + wm * 144 + aoff;            // Ah
        const uint32_t Bbase = stq + BOFF + wn * 144 + boff;     // Bh

#pragma unroll
        for (int ks = 0; ks < 4; ks++) {
            const uint32_t ab = Abase + ks * 32;
            const uint32_t bb = Bbase + ks * 32;
            uint32_t ah[4][4], al[4][4], bh[4][2], bl[4][2];
#pragma unroll
            for (int mt = 0; mt < 4; mt++) {
                LDSM4(ah[mt][0], ah[mt][1], ah[mt][2], ah[mt][3], ab + mt * 2304);
                if (NA == 2)
                    LDSM4(al[mt][0], al[mt][1], al[mt][2], al[mt][3],
                          ab + TILE_B + mt * 2304);
            }
#pragma unroll
            for (int p = 0; p < 2; p++) {
                LDSM4(bh[2*p][0], bh[2*p][1], bh[2*p+1][0], bh[2*p+1][1],
                      bb + p * 2304);
                if (NB == 2)
                    LDSM4(bl[2*p][0], bl[2*p][1], bl[2*p+1][0], bl[2*p+1][1],
                          bb + TILE_B + p * 2304);
            }
#pragma unroll
            for (int mt = 0; mt < 4; mt++)
#pragma unroll
                for (int nt = 0; nt < 4; nt++)
                    mma16816(acc[mt][nt], ah[mt], bh[nt]);
            if (NA == 2) {
#pragma unroll
                for (int mt = 0; mt < 4; mt++)
#pragma unroll
                    for (int nt = 0; nt < 4; nt++)
                        mma16816(acc[mt][nt], al[mt], bh[nt]);
            }
            if (NB == 2) {
#pragma unroll
                for (int mt = 0; mt < 4; mt++)
#pragma unroll
                    for (int nt = 0; nt < 4; nt++)
                        mma16816(acc[mt][nt], ah[mt], bl[nt]);
            }
        }

        if (ch + 2 < nch) {
            __syncthreads();
            issue(ch + 2, ch & 1);
        }
    }

    // ---------------- epilogue -------------------------------------------------
    if (EPI <= 3 || EPI == 7 || EPI == 8) {
#pragma unroll
        for (int mt = 0; mt < 4; mt++)
#pragma unroll
            for (int nt = 0; nt < 4; nt++) {
                const int ri2 = wm + mt * 16 + gr;
                const int ci  = wn + nt * 8 + 2 * lc;
#pragma unroll
                for (int hf = 0; hf < 2; hf++) {
                    const int r = row0 + ri2 + hf * 8;
                    const int c = col0 + ci;
                    float v0 = acc[mt][nt][hf * 2 + 0];
                    float v1 = acc[mt][nt][hf * 2 + 1];
                    if (EPI == 7) { v0 = fmaxf(v0, 0.f); v1 = fmaxf(v1, 0.f); }
                    if (EPI == 3 || EPI == 8) {
                        float2 rv = *(const float2*)&R[(size_t)r * Ntot + c];
                        v0 += rv.x; v1 += rv.y;
                        *(float2*)&Cf[(size_t)r * ldC + c] = make_float2(v0, v1);
                    }
                    if (EPI == 0) {
                        *(float2*)&Cf[(size_t)r * ldC + c] = make_float2(v0, v1);
                    } else if (EPI == 7 || EPI == 8) {
                        *(__half2*)&Ch[(size_t)r * ldC + c] =
                            __halves2half2(__float2half_rn(v0), __float2half_rn(v1));
                    } else {
                        fp16 h0, l0, h1, l1;
                        split2(v0, h0, l0); split2(v1, h1, l1);
                        *(__half2*)&Ch[(size_t)r * ldC + c] = __halves2half2(h0, h1);
                        *(__half2*)&Cl[(size_t)r * ldC + c] = __halves2half2(l0, l1);
                    }
                }
            }
    } else {
        // transposed epilogues via fp32 smem buffer [128][130]
        __syncthreads();
        float* Tb = (float*)smem_raw;
#pragma unroll
        for (int mt = 0; mt < 4; mt++)
#pragma unroll
            for (int nt = 0; nt < 4; nt++) {
                const int ri2 = wm + mt * 16 + gr;
                const int ci  = wn + nt * 8 + 2 * lc;
#pragma unroll
                for (int hf = 0; hf < 2; hf++) {
                    const int rr = ri2 + hf * 8;
                    float v0 = acc[mt][nt][hf * 2 + 0];
                    float v1 = acc[mt][nt][hf * 2 + 1];
                    if (EPI == 5) {
                        float2 rv = *(const float2*)
                            &R[(size_t)(row0 + rr) * Ntot + col0 + ci];
                        v0 += rv.x; v1 += rv.y;
                    }
                    Tb[rr * 130 + ci]     = v0;
                    Tb[rr * 130 + ci + 1] = v1;
                }
            }
        __syncthreads();
        const int j  = tid & 127;          // output row within tile = GEMM col
        const int sg = tid >> 7;
        const int rb = sg * 64;
        if (EPI == 4 || EPI == 6) {
#pragma unroll
            for (int g = 0; g < 16; g++) {
                uint32_t hp[2], lp[2];
#pragma unroll
                for (int e = 0; e < 2; e++) {
                    float v0 = Tb[(rb + g * 4 + 2 * e)     * 130 + j];
                    float v1 = Tb[(rb + g * 4 + 2 * e + 1) * 130 + j];
                    fp16 h0, l0, h1, l1;
                    split2(v0, h0, l0); split2(v1, h1, l1);
                    __half2 hh = __halves2half2(h0, h1), ll = __halves2half2(l0, l1);
                    hp[e] = *(uint32_t*)&hh; lp[e] = *(uint32_t*)&ll;
                }
                size_t o = (size_t)(col0 + j) * ldC + row0 + rb + g * 4;
                *(uint2*)&Ch[o] = make_uint2(hp[0], hp[1]);
                if (EPI == 4)
                    *(uint2*)&Cl[o] = make_uint2(lp[0], lp[1]);
            }
        } else {  // EPI 5
#pragma unroll
            for (int g = 0; g < 16; g++) {
                float4 v;
                v.x = Tb[(rb + g * 4 + 0) * 130 + j];
                v.y = Tb[(rb + g * 4 + 1) * 130 + j];
                v.z = Tb[(rb + g * 4 + 2) * 130 + j];
                v.w = Tb[(rb + g * 4 + 3) * 130 + j];
                *(float4*)&Cf[(size_t)(col0 + j) * ldC + row0 + rb + g * 4] = v;
            }
        }
    }
}

// ---------------- transpose + fp16 split -------------------------------------
__global__ __launch_bounds__(256)
void tsplit(const float* __restrict__ in, fp16* __restrict__ oh,
            fp16* __restrict__ ol, float* __restrict__ of, int Rr, int Cc)
{
    __shared__ float t[32][33];
    int x = blockIdx.x * 32 + threadIdx.x;
    int y = blockIdx.y * 32 + threadIdx.y;
#pragma unroll
    for (int i = 0; i < 32; i += 8)
        t[threadIdx.y + i][threadIdx.x] = in[(size_t)(y + i) * Cc + x];
    __syncthreads();
    int xo = blockIdx.y * 32 + threadIdx.x;
    int yo = blockIdx.x * 32 + threadIdx.y;
#pragma unroll
    for (int i = 0; i < 32; i += 8) {
        float v = t[threadIdx.x][threadIdx.y + i];
        size_t o = (size_t)(yo + i) * Rr + xo;
        fp16 h, l; split2(v, h, l);
        oh[o] = h; if (ol) ol[o] = l;
        if (of) of[o] = v;
    }
}

// ---------------- straight fp16 split ----------------------------------------
__global__ __launch_bounds__(256)
void ssplit(const float* __restrict__ in, fp16* __restrict__ oh,
            fp16* __restrict__ ol, int n)
{
    int i = blockIdx.x * 256 + threadIdx.x;
    if (i < n) {
        fp16 h, l; split2(in[i], h, l);
        oh[i] = h; ol[i] = l;
    }
}

// ---------------- causal softmax -> fp16 A (hi only) -------------------------
__global__ __launch_bounds__(256)
void softmax_fp16(const float* __restrict__ S, fp16* __restrict__ Ah)
{
    const int row = blockIdx.x;
    const int len = row + 1;
    __shared__ float buf[NTOK];
    __shared__ float red[256];
    const int tid = threadIdx.x;
    const float* p = S + (size_t)row * NTOK;

    float m = NEG_INF;
    for (int j = tid; j < len; j += 256) { float v = p[j]; buf[j] = v; m = fmaxf(m, v); }
    red[tid] = m; __syncthreads();
    for (int s = 128; s > 0; s >>= 1) {
        if (tid < s) red[tid] = fmaxf(red[tid], red[tid + s]);
        __syncthreads();
    }
    m = red[0]; __syncthreads();

    float sum = 0.f;
    for (int j = tid; j < len; j += 256) { float e = __expf(buf[j] - m); buf[j] = e; sum += e; }
    red[tid] = sum; __syncthreads();
    for (int s = 128; s > 0; s >>= 1) {
        if (tid < s) red[tid] += red[tid + s];
        __syncthreads();
    }
    const float inv = 1.f / red[0];

    const int be = ((row >> 7) + 1) << 7;   // zero-fill to row-block end for CKLIM
    for (int j = tid; j < be; j += 256) {
        float v = (j < len) ? buf[j] * inv : 0.f;
        Ah[(size_t)row * NTOK + j] = __float2half_rn(v);
    }
}

// ---------------- driver ------------------------------------------------------
#define DS3 (2 * 4 * TILE_B)   // 147456
#define DS1 (2 * 2 * TILE_B)   //  73728 -> 2 CTAs/SM

extern "C" void kernel_launch(void* const* d_in, const int* in_sizes, int n_in,
                              void* d_out, int out_size) {
    (void)in_sizes; (void)n_in; (void)out_size;
    const float* X      = (const float*)d_in[0];
    const float* W_Q    = (const float*)d_in[1];
    const float* W_K    = (const float*)d_in[2];
    const float* W_V    = (const float*)d_in[3];
    const float* W_O    = (const float*)d_in[4];
    const float* mlp_in = (const float*)d_in[5];
    const float* mlp_out= (const float*)d_in[6];
    float* out = (float*)d_out;

    float *Xt, *S, *X2;
    fp16 *Xth, *Xtl, *PAh, *PAl, *PBh, *PBl, *POh, *POl;
    fp16 *W4h, *W5h, *Qmh, *Qml, *RHth, *RHtl;
    fp16 *Ah, *X2h, *Hh;
    cudaGetSymbolAddress((void**)&Xt,  g_Xt);   cudaGetSymbolAddress((void**)&Xth, g_Xth);
    cudaGetSymbolAddress((void**)&Xtl, g_Xtl);  cudaGetSymbolAddress((void**)&PAh, g_PAh);
    cudaGetSymbolAddress((void**)&PAl, g_PAl);  cudaGetSymbolAddress((void**)&PBh, g_PBh);
    cudaGetSymbolAddress((void**)&PBl, g_PBl);  cudaGetSymbolAddress((void**)&POh, g_POh);
    cudaGetSymbolAddress((void**)&POl, g_POl);  cudaGetSymbolAddress((void**)&W4h, g_W4h);
    cudaGetSymbolAddress((void**)&W5h, g_W5h);  cudaGetSymbolAddress((void**)&Qmh, g_Qmh);
    cudaGetSymbolAddress((void**)&Qml, g_Qml);  cudaGetSymbolAddress((void**)&RHth, g_RHth);
    cudaGetSymbolAddress((void**)&RHtl, g_RHtl); cudaGetSymbolAddress((void**)&S,  g_S);
    cudaGetSymbolAddress((void**)&Ah,  g_Ah);
    cudaGetSymbolAddress((void**)&X2,  g_X2);   cudaGetSymbolAddress((void**)&X2h, g_X2h);
    cudaGetSymbolAddress((void**)&Hh,  g_Hh);

    cudaFuncSetAttribute(gemm_mma<4,3,0,0,1>, cudaFuncAttributeMaxDynamicSharedMemorySize, DS3);
    cudaFuncSetAttribute(gemm_mma<1,3,0,0,1>, cudaFuncAttributeMaxDynamicSharedMemorySize, DS3);
    cudaFuncSetAttribute(gemm_mma<0,3,1,0,1>, cudaFuncAttributeMaxDynamicSharedMemorySize, DS3);
    cudaFuncSetAttribute(gemm_mma<6,1,0,0,2>, cudaFuncAttributeMaxDynamicSharedMemorySize, DS1);
    cudaFuncSetAttribute(gemm_mma<8,1,0,1,2>, cudaFuncAttributeMaxDynamicSharedMemorySize, DS1);
    cudaFuncSetAttribute(gemm_mma<7,1,0,0,2>, cudaFuncAttributeMaxDynamicSharedMemorySize, DS1);
    cudaFuncSetAttribute(gemm_mma<5,1,0,0,2>, cudaFuncAttributeMaxDynamicSharedMemorySize, DS1);

    const size_t WSZ = (size_t)DM * DM;
    dim3 tb(32, 8);
    dim3 gw(DM / 32, DM / 32);

    // preprocessing: transposes + splits
    tsplit<<<dim3(NTOK / 32, DM / 32), tb>>>(X, Xth, Xtl, Xt, DM, NTOK);
    ssplit<<<(int)(WSZ / 256), 256>>>(W_Q, PAh, PAl, (int)WSZ);            // A0 = Wq
    ssplit<<<(int)(WSZ / 256), 256>>>(W_V, PAh + WSZ, PAl + WSZ, (int)WSZ);// A1 = Wv
    ssplit<<<(int)(WSZ / 256), 256>>>(W_K, PBh, PBl, (int)WSZ);            // B0 = Wk
    tsplit<<<gw, tb>>>(W_O, PBh + WSZ, PBl + WSZ, nullptr, DM, DM);        // B1 = Wo^T
    tsplit<<<gw, tb>>>(mlp_in,  W4h, nullptr, nullptr, DM, DM);
    tsplit<<<gw, tb>>>(mlp_out, W5h, nullptr, nullptr, DM, DM);

    dim3 blk(256);
    dim3 grid_p(DM / 128, DM / 128, 2);    // z-batched preps: M^T and Wvo^T
    dim3 grid_d(DM / 128, NTOK / 128);
    dim3 grid_s(NTOK / 128, NTOK / 128);

    // preps (3-term): z=0: M = Wq@Wk^T -> M^T ; z=1: Wvo = Wv@Wo -> Wvo^T
    gemm_mma<4,3,0,0,1><<<grid_p, blk, DS3>>>(PAh, PAl, PBh, PBl,
                                              nullptr, nullptr, POh, POl, DM, DM, DM);
    // Qm = Xt @ M  (3-term)  [B = M^T]
    gemm_mma<1,3,0,0,1><<<grid_d, blk, DS3>>>(Xth, Xtl, POh, POl,
                                              nullptr, nullptr, Qmh, Qml, DM, DM, DM);
    // S = Qm @ Xt^T  (3-term, causal skip)
    gemm_mma<0,3,1,0,1><<<grid_s, blk, DS3>>>(Qmh, Qml, Xth, Xtl,
                                              nullptr, S, nullptr, nullptr, NTOK, DM, NTOK);
    // softmax rows -> A fp16 hi (zero-filled to 128-block end)
    softmax_fp16<<<NTOK, 256>>>(S, Ah);
    // RH = Xth @ Wvo_h  (1-term) -> RH^T hi only
    gemm_mma<6,1,0,0,2><<<grid_d, blk, DS1>>>(Xth, nullptr, POh + WSZ, nullptr,
                                              nullptr, nullptr, RHth, RHtl, DM, DM, NTOK);
    // X2 = Xt + A @ RH  (1-term, K bounded by causality) -> fp32 + hi only
    gemm_mma<8,1,0,1,2><<<grid_d, blk, DS1>>>(Ah, nullptr, RHth, nullptr,
                                              Xt, X2, X2h, nullptr, DM, NTOK, DM);
    // H = relu(X2h @ mlp_in_h)  (1-term) -> hi only
    gemm_mma<7,1,0,0,2><<<grid_d, blk, DS1>>>(X2h, nullptr, W4h, nullptr,
                                              nullptr, nullptr, Hh, nullptr, DM, DM, DM);
    // out = (X2 + Hh @ mlp_out_h)^T  (1-term)
    gemm_mma<5,1,0,0,2><<<grid_d, blk, DS1>>>(Hh, nullptr, W5h, nullptr,
                                              X2, out, nullptr, nullptr, DM, DM, NTOK);
}